// round 6
// baseline (speedup 1.0000x reference)
#include <cuda_runtime.h>

// Cubic Bezier spline evaluation — 16 samples/thread, 4 front-batched vector
// loads (MLP=4), packed f32x2 Horner, evict-first output stores.
//   d_in[0]: t              float32 [N]      (sorted, in [0,1))
//   d_in[1]: control_points float32 [S*2, 2]
//   d_in[2]: joint_points   float32 [S+1, 2]
// Output: float32 [N, 2]

struct __align__(8) F2 { float x, y; };
typedef unsigned long long u64;

__device__ __forceinline__ u64 pack2(float lo, float hi) {
    u64 r; asm("mov.b64 %0, {%1, %2};" : "=l"(r) : "f"(lo), "f"(hi)); return r;
}
__device__ __forceinline__ u64 fma2(u64 a, u64 b, u64 c) {
    u64 d; asm("fma.rn.f32x2 %0, %1, %2, %3;" : "=l"(d) : "l"(a), "l"(b), "l"(c));
    return d;
}
__device__ __forceinline__ void st_cs_v2u64(void* p, u64 a, u64 b) {
    asm volatile("st.global.cs.v2.u64 [%0], {%1, %2};"
                 :: "l"(p), "l"(a), "l"(b) : "memory");
}

// Packed power-basis coefficients for one segment: each u64 = (x, y) fp32 pair.
struct CoeffsP { u64 c0, c1, c2, c3; };

__device__ __forceinline__ CoeffsP make_coeffs(int seg,
                                               const float4* __restrict__ ctrl4,
                                               const F2* __restrict__ joint) {
    F2 P0 = joint[seg];
    F2 P3 = joint[seg + 1];
    float4 cc = ctrl4[seg];          // (P1.x, P1.y, P2.x, P2.y)

    CoeffsP c;
    c.c0 = pack2(P0.x, P0.y);
    c.c1 = pack2(3.0f * (cc.x - P0.x),
                 3.0f * (cc.y - P0.y));
    c.c2 = pack2(3.0f * (P0.x - 2.0f * cc.x + cc.z),
                 3.0f * (P0.y - 2.0f * cc.y + cc.w));
    c.c3 = pack2(fmaf(3.0f, cc.x - cc.z, P3.x - P0.x),
                 fmaf(3.0f, cc.y - cc.w, P3.y - P0.y));
    return c;
}

__device__ __forceinline__ u64 eval_packed(const CoeffsP& c, float lt) {
    u64 ltp = pack2(lt, lt);
    u64 acc = fma2(c.c3, ltp, c.c2);
    acc     = fma2(acc,  ltp, c.c1);
    acc     = fma2(acc,  ltp, c.c0);
    return acc;                       // == (x, y) output pair
}

__device__ __forceinline__ void seg_lt(float tval, float Sf, int S,
                                       int& seg, float& lt) {
    float u  = tval * Sf;
    float fs = floorf(u);
    int   s  = (int)fs;
    float l  = u - fs;
    if (s >= S) { s = S - 1; l = 1.0f; }
    seg = s; lt = l;
}

__global__ void __launch_bounds__(256, 5)
spline_kernel(const float* __restrict__ t,
              const float4* __restrict__ ctrl4,
              const F2* __restrict__ joint,
              float* __restrict__ out,
              int n, int S, float Sf)
{
    int gid  = blockIdx.x * blockDim.x + threadIdx.x;   // group of 16 samples
    long long base = (long long)gid * 16;

    if (base + 15 < n) {
        // Front-batch ALL t loads: 4 independent LDG.128 in flight (MLP=4).
        const float4* tp = reinterpret_cast<const float4*>(t + base);
        float4 v0 = tp[0];
        float4 v1 = tp[1];
        float4 v2 = tp[2];
        float4 v3 = tp[3];

        float tv[16] = {v0.x,v0.y,v0.z,v0.w, v1.x,v1.y,v1.z,v1.w,
                        v2.x,v2.y,v2.z,v2.w, v3.x,v3.y,v3.z,v3.w};
        int   seg[16];
        float lt[16];
        #pragma unroll
        for (int k = 0; k < 16; ++k) seg_lt(tv[k], Sf, S, seg[k], lt[k]);

        char* ob = reinterpret_cast<char*>(out + 2 * base);

        if (seg[0] == seg[15]) {
            // Fast path: all 16 samples in one segment (~99.2% of threads).
            CoeffsP c = make_coeffs(seg[0], ctrl4, joint);
            #pragma unroll
            for (int k = 0; k < 16; k += 2) {
                u64 ra = eval_packed(c, lt[k]);
                u64 rb = eval_packed(c, lt[k + 1]);
                st_cs_v2u64(ob + 8 * k, ra, rb);
            }
        } else {
            #pragma unroll
            for (int k = 0; k < 16; k += 2) {
                CoeffsP ca = make_coeffs(seg[k], ctrl4, joint);
                u64 ra = eval_packed(ca, lt[k]);
                CoeffsP cb = make_coeffs(seg[k + 1], ctrl4, joint);
                u64 rb = eval_packed(cb, lt[k + 1]);
                st_cs_v2u64(ob + 8 * k, ra, rb);
            }
        }
    } else {
        for (long long k = base; k < n; ++k) {
            int s; float l;
            seg_lt(t[k], Sf, S, s, l);
            CoeffsP c = make_coeffs(s, ctrl4, joint);
            u64 r = eval_packed(c, l);
            reinterpret_cast<u64*>(out)[k] = r;
        }
    }
}

extern "C" void kernel_launch(void* const* d_in, const int* in_sizes, int n_in,
                              void* d_out, int out_size)
{
    const float*  t     = (const float*)d_in[0];
    const float4* ctrl4 = (const float4*)d_in[1];
    const F2*     joint = (const F2*)d_in[2];
    float*        out   = (float*)d_out;

    int n = in_sizes[0];
    int S = in_sizes[2] / 2 - 1;       // joint_points has (S+1)*2 floats
    float Sf = (float)S;

    int ngroups = (n + 15) / 16;
    int threads = 256;
    int blocks  = (ngroups + threads - 1) / threads;
    spline_kernel<<<blocks, threads>>>(t, ctrl4, joint, out, n, S, Sf);
}

// round 9
// speedup vs baseline: 1.4443x; 1.4443x over previous
#include <cuda_runtime.h>

// Cubic Bezier spline evaluation — R1 structure (proven fastest: 4 samples/
// thread, 256 threads, 32 regs, occ 81%) + write-through output stores so the
// 64 MB output stream does not write-allocate in L2. Keeps t L2-resident
// across graph replays and avoids the deferred dirty-writeback wave.
//   d_in[0]: t              float32 [N]      (sorted, in [0,1))
//   d_in[1]: control_points float32 [S*2, 2]
//   d_in[2]: joint_points   float32 [S+1, 2]
// Output: float32 [N, 2]

struct __align__(8) F2 { float x, y; };

__device__ __forceinline__ void st_wt_f4(void* p, float4 v) {
    asm volatile("st.global.wt.v4.f32 [%0], {%1, %2, %3, %4};"
                 :: "l"(p), "f"(v.x), "f"(v.y), "f"(v.z), "f"(v.w) : "memory");
}

__device__ __forceinline__ F2 eval_one(float t, float Sf, int S,
                                       const F2* __restrict__ ctrl,
                                       const F2* __restrict__ joint) {
    float u  = t * Sf;                 // Sf = 4096 -> exact scaling
    float fs = floorf(u);
    int   seg = (int)fs;
    float lt  = u - fs;
    if (seg >= S) { seg = S - 1; lt = 1.0f; }   // parity with reference edge case
    F2 P0 = joint[seg];
    F2 P3 = joint[seg + 1];
    F2 P1 = ctrl[2 * seg];
    F2 P2 = ctrl[2 * seg + 1];

    float c1x = 3.0f * (P1.x - P0.x);
    float c2x = 3.0f * (P0.x - 2.0f * P1.x + P2.x);
    float c3x = fmaf(3.0f, P1.x - P2.x, P3.x - P0.x);
    float xr  = fmaf(fmaf(fmaf(c3x, lt, c2x), lt, c1x), lt, P0.x);

    float c1y = 3.0f * (P1.y - P0.y);
    float c2y = 3.0f * (P0.y - 2.0f * P1.y + P2.y);
    float c3y = fmaf(3.0f, P1.y - P2.y, P3.y - P0.y);
    float yr  = fmaf(fmaf(fmaf(c3y, lt, c2y), lt, c1y), lt, P0.y);

    F2 r; r.x = xr; r.y = yr;
    return r;
}

__global__ void __launch_bounds__(256)
spline_kernel(const float* __restrict__ t,
              const F2* __restrict__ ctrl,
              const F2* __restrict__ joint,
              float* __restrict__ out,
              int n, int S, float Sf)
{
    int i4 = blockIdx.x * blockDim.x + threadIdx.x;   // group of 4 samples
    int base = i4 * 4;
    if (base + 3 < n) {
        float4 tv = *reinterpret_cast<const float4*>(t + base);
        F2 r0 = eval_one(tv.x, Sf, S, ctrl, joint);
        F2 r1 = eval_one(tv.y, Sf, S, ctrl, joint);
        F2 r2 = eval_one(tv.z, Sf, S, ctrl, joint);
        F2 r3 = eval_one(tv.w, Sf, S, ctrl, joint);
        float* o = out + 2 * base;
        st_wt_f4(o,     make_float4(r0.x, r0.y, r1.x, r1.y));
        st_wt_f4(o + 4, make_float4(r2.x, r2.y, r3.x, r3.y));
    } else {
        for (int k = base; k < n; ++k) {
            F2 r = eval_one(t[k], Sf, S, ctrl, joint);
            out[2 * k]     = r.x;
            out[2 * k + 1] = r.y;
        }
    }
}

extern "C" void kernel_launch(void* const* d_in, const int* in_sizes, int n_in,
                              void* d_out, int out_size)
{
    const float* t     = (const float*)d_in[0];
    const F2*    ctrl  = (const F2*)d_in[1];
    const F2*    joint = (const F2*)d_in[2];
    float*       out   = (float*)d_out;

    int n = in_sizes[0];
    int S = in_sizes[2] / 2 - 1;       // joint_points has (S+1)*2 floats
    float Sf = (float)S;

    int ngroups = (n + 3) / 4;
    int threads = 256;
    int blocks  = (ngroups + threads - 1) / threads;
    spline_kernel<<<blocks, threads>>>(t, ctrl, joint, out, n, S, Sf);
}

// round 10
// speedup vs baseline: 1.5617x; 1.0813x over previous
#include <cuda_runtime.h>

// Cubic Bezier spline evaluation — R9 structure (4 samples/thread, 256 thr,
// occ 82%, WT stores) + warp-uniform segment broadcast: t is sorted, a warp
// spans 128 consecutive samples, and segments hold ~2048 samples, so ~94% of
// warps lie entirely in one segment. Uniform path: broadcast-load the 4
// Bezier points once (all lanes same address -> 1 L1 wavefront/load), fold
// the Bezier matrix once per thread, then 4 cheap Horner evals.
//   d_in[0]: t              float32 [N]      (sorted, in [0,1))
//   d_in[1]: control_points float32 [S*2, 2]
//   d_in[2]: joint_points   float32 [S+1, 2]
// Output: float32 [N, 2]

struct __align__(8) F2 { float x, y; };

__device__ __forceinline__ void st_wt_f4(void* p, float4 v) {
    asm volatile("st.global.wt.v4.f32 [%0], {%1, %2, %3, %4};"
                 :: "l"(p), "f"(v.x), "f"(v.y), "f"(v.z), "f"(v.w) : "memory");
}

// Power-basis coefficients (Bezier matrix folded into points), both axes.
struct Coeffs {
    float c0x, c1x, c2x, c3x;
    float c0y, c1y, c2y, c3y;
};

__device__ __forceinline__ Coeffs make_coeffs(int seg,
                                              const float4* __restrict__ ctrl4,
                                              const F2* __restrict__ joint) {
    F2 P0 = joint[seg];
    F2 P3 = joint[seg + 1];
    float4 cc = ctrl4[seg];          // (P1.x, P1.y, P2.x, P2.y), 16B aligned

    Coeffs c;
    c.c0x = P0.x;
    c.c1x = 3.0f * (cc.x - P0.x);
    c.c2x = 3.0f * (P0.x - 2.0f * cc.x + cc.z);
    c.c3x = fmaf(3.0f, cc.x - cc.z, P3.x - P0.x);
    c.c0y = P0.y;
    c.c1y = 3.0f * (cc.y - P0.y);
    c.c2y = 3.0f * (P0.y - 2.0f * cc.y + cc.w);
    c.c3y = fmaf(3.0f, cc.y - cc.w, P3.y - P0.y);
    return c;
}

__device__ __forceinline__ F2 horner(const Coeffs& c, float lt) {
    F2 r;
    r.x = fmaf(fmaf(fmaf(c.c3x, lt, c.c2x), lt, c.c1x), lt, c.c0x);
    r.y = fmaf(fmaf(fmaf(c.c3y, lt, c.c2y), lt, c.c1y), lt, c.c0y);
    return r;
}

__device__ __forceinline__ void seg_lt(float tval, float Sf, int S,
                                       int& seg, float& lt) {
    float u  = tval * Sf;              // Sf = 4096 -> exact scaling
    float fs = floorf(u);
    int   s  = (int)fs;
    float l  = u - fs;
    if (s >= S) { s = S - 1; l = 1.0f; }   // parity with reference edge case
    seg = s; lt = l;
}

__global__ void __launch_bounds__(256)
spline_kernel(const float* __restrict__ t,
              const float4* __restrict__ ctrl4,
              const F2* __restrict__ joint,
              float* __restrict__ out,
              int n, int S, float Sf)
{
    int gid  = blockIdx.x * blockDim.x + threadIdx.x;   // group of 4 samples
    int base = gid * 4;

    if (base + 3 < n) {
        float4 tv = *reinterpret_cast<const float4*>(t + base);

        int   sg[4];
        float lt[4];
        seg_lt(tv.x, Sf, S, sg[0], lt[0]);
        seg_lt(tv.y, Sf, S, sg[1], lt[1]);
        seg_lt(tv.z, Sf, S, sg[2], lt[2]);
        seg_lt(tv.w, Sf, S, sg[3], lt[3]);

        // Warp spans 128 sorted samples: uniform iff first and last agree.
        unsigned mask = 0xFFFFFFFFu;
        int sFirst = __shfl_sync(mask, sg[0], 0);
        int sLast  = __shfl_sync(mask, sg[3], 31);

        F2 r0, r1, r2, r3;
        if (sFirst == sLast) {
            // Uniform path (~94% of warps): broadcast loads, one assembly.
            Coeffs c = make_coeffs(sFirst, ctrl4, joint);
            r0 = horner(c, lt[0]);
            r1 = horner(c, lt[1]);
            r2 = horner(c, lt[2]);
            r3 = horner(c, lt[3]);
        } else {
            Coeffs ca = make_coeffs(sg[0], ctrl4, joint);
            r0 = horner(ca, lt[0]);
            Coeffs cb = make_coeffs(sg[1], ctrl4, joint);
            r1 = horner(cb, lt[1]);
            Coeffs cc = make_coeffs(sg[2], ctrl4, joint);
            r2 = horner(cc, lt[2]);
            Coeffs cd = make_coeffs(sg[3], ctrl4, joint);
            r3 = horner(cd, lt[3]);
        }

        float* o = out + 2 * base;
        st_wt_f4(o,     make_float4(r0.x, r0.y, r1.x, r1.y));
        st_wt_f4(o + 4, make_float4(r2.x, r2.y, r3.x, r3.y));
    } else {
        for (int k = base; k < n; ++k) {
            int s; float l;
            seg_lt(t[k], Sf, S, s, l);
            Coeffs c = make_coeffs(s, ctrl4, joint);
            F2 r = horner(c, l);
            out[2 * k]     = r.x;
            out[2 * k + 1] = r.y;
        }
    }
}

extern "C" void kernel_launch(void* const* d_in, const int* in_sizes, int n_in,
                              void* d_out, int out_size)
{
    const float*  t     = (const float*)d_in[0];
    const float4* ctrl4 = (const float4*)d_in[1];   // 2 ctrl pts/segment = 16B
    const F2*     joint = (const F2*)d_in[2];
    float*        out   = (float*)d_out;

    int n = in_sizes[0];
    int S = in_sizes[2] / 2 - 1;       // joint_points has (S+1)*2 floats
    float Sf = (float)S;

    int ngroups = (n + 3) / 4;
    int threads = 256;
    int blocks  = (ngroups + threads - 1) / threads;
    spline_kernel<<<blocks, threads>>>(t, ctrl4, joint, out, n, S, Sf);
}

// round 11
// speedup vs baseline: 1.5641x; 1.0015x over previous
#include <cuda_runtime.h>

// Cubic Bezier spline evaluation — R10 compute (4 samples/thread, warp-uniform
// segment broadcast) + SMEM-staged output drained by one cp.async.bulk (TMA)
// per block. Removes per-thread STG.128s from the LSU/L1 path entirely.
//   d_in[0]: t              float32 [N]      (sorted, in [0,1))
//   d_in[1]: control_points float32 [S*2, 2]
//   d_in[2]: joint_points   float32 [S+1, 2]
// Output: float32 [N, 2]

struct __align__(8) F2 { float x, y; };

// Power-basis coefficients (Bezier matrix folded into points), both axes.
struct Coeffs {
    float c0x, c1x, c2x, c3x;
    float c0y, c1y, c2y, c3y;
};

__device__ __forceinline__ Coeffs make_coeffs(int seg,
                                              const float4* __restrict__ ctrl4,
                                              const F2* __restrict__ joint) {
    F2 P0 = joint[seg];
    F2 P3 = joint[seg + 1];
    float4 cc = ctrl4[seg];          // (P1.x, P1.y, P2.x, P2.y), 16B aligned

    Coeffs c;
    c.c0x = P0.x;
    c.c1x = 3.0f * (cc.x - P0.x);
    c.c2x = 3.0f * (P0.x - 2.0f * cc.x + cc.z);
    c.c3x = fmaf(3.0f, cc.x - cc.z, P3.x - P0.x);
    c.c0y = P0.y;
    c.c1y = 3.0f * (cc.y - P0.y);
    c.c2y = 3.0f * (P0.y - 2.0f * cc.y + cc.w);
    c.c3y = fmaf(3.0f, cc.y - cc.w, P3.y - P0.y);
    return c;
}

__device__ __forceinline__ F2 horner(const Coeffs& c, float lt) {
    F2 r;
    r.x = fmaf(fmaf(fmaf(c.c3x, lt, c.c2x), lt, c.c1x), lt, c.c0x);
    r.y = fmaf(fmaf(fmaf(c.c3y, lt, c.c2y), lt, c.c1y), lt, c.c0y);
    return r;
}

__device__ __forceinline__ void seg_lt(float tval, float Sf, int S,
                                       int& seg, float& lt) {
    float u  = tval * Sf;              // Sf = 4096 -> exact scaling
    float fs = floorf(u);
    int   s  = (int)fs;
    float l  = u - fs;
    if (s >= S) { s = S - 1; l = 1.0f; }   // parity with reference edge case
    seg = s; lt = l;
}

// 256 threads * 4 samples * 2 floats = 2048 floats = 8 KB per block tile.
#define TILE_FLOATS 2048

__global__ void __launch_bounds__(256)
spline_kernel(const float* __restrict__ t,
              const float4* __restrict__ ctrl4,
              const F2* __restrict__ joint,
              float* __restrict__ out,
              int n, int S, float Sf)
{
    __shared__ __align__(16) float tile[TILE_FLOATS];

    int tid  = threadIdx.x;
    int gid  = blockIdx.x * blockDim.x + tid;   // group of 4 samples
    int base = gid * 4;
    int blockBase = blockIdx.x * (int)blockDim.x * 4;       // first sample of block
    bool fullBlock = (blockBase + TILE_FLOATS / 2) <= n;    // all 1024 samples valid

    if (base + 3 < n) {
        float4 tv = *reinterpret_cast<const float4*>(t + base);

        int   sg[4];
        float lt[4];
        seg_lt(tv.x, Sf, S, sg[0], lt[0]);
        seg_lt(tv.y, Sf, S, sg[1], lt[1]);
        seg_lt(tv.z, Sf, S, sg[2], lt[2]);
        seg_lt(tv.w, Sf, S, sg[3], lt[3]);

        // Warp spans 128 sorted samples: uniform iff first and last agree.
        unsigned mask = 0xFFFFFFFFu;
        int sFirst = __shfl_sync(mask, sg[0], 0);
        int sLast  = __shfl_sync(mask, sg[3], 31);

        F2 r0, r1, r2, r3;
        if (sFirst == sLast) {
            // Uniform path (~94% of warps): broadcast loads, one assembly.
            Coeffs c = make_coeffs(sFirst, ctrl4, joint);
            r0 = horner(c, lt[0]);
            r1 = horner(c, lt[1]);
            r2 = horner(c, lt[2]);
            r3 = horner(c, lt[3]);
        } else {
            Coeffs ca = make_coeffs(sg[0], ctrl4, joint);
            r0 = horner(ca, lt[0]);
            Coeffs cb = make_coeffs(sg[1], ctrl4, joint);
            r1 = horner(cb, lt[1]);
            Coeffs cc = make_coeffs(sg[2], ctrl4, joint);
            r2 = horner(cc, lt[2]);
            Coeffs cd = make_coeffs(sg[3], ctrl4, joint);
            r3 = horner(cd, lt[3]);
        }

        if (fullBlock) {
            // Stage into SMEM tile (linear image of the output block).
            float4* tp4 = reinterpret_cast<float4*>(tile) + tid * 2;
            tp4[0] = make_float4(r0.x, r0.y, r1.x, r1.y);
            tp4[1] = make_float4(r2.x, r2.y, r3.x, r3.y);
        } else {
            float4* o = reinterpret_cast<float4*>(out + 2 * base);
            o[0] = make_float4(r0.x, r0.y, r1.x, r1.y);
            o[1] = make_float4(r2.x, r2.y, r3.x, r3.y);
        }
    } else {
        for (int k = base; k < n; ++k) {
            int s; float l;
            seg_lt(t[k], Sf, S, s, l);
            Coeffs c = make_coeffs(s, ctrl4, joint);
            F2 r = horner(c, l);
            out[2 * k]     = r.x;
            out[2 * k + 1] = r.y;
        }
    }

    if (fullBlock) {
        __syncthreads();
        if (tid == 0) {
            // Order generic smem stores before the async-proxy bulk copy.
            asm volatile("fence.proxy.async.shared::cta;" ::: "memory");
            unsigned saddr;
            asm("{ .reg .u64 tmp; cvta.to.shared.u64 tmp, %1; cvt.u32.u64 %0, tmp; }"
                : "=r"(saddr) : "l"(tile));
            float* gdst = out + 2 * blockBase;
            asm volatile("cp.async.bulk.global.shared::cta.bulk_group [%0], [%1], %2;"
                         :: "l"(gdst), "r"(saddr), "n"(TILE_FLOATS * 4) : "memory");
            asm volatile("cp.async.bulk.commit_group;" ::: "memory");
            asm volatile("cp.async.bulk.wait_group 0;" ::: "memory");
        }
    }
}

extern "C" void kernel_launch(void* const* d_in, const int* in_sizes, int n_in,
                              void* d_out, int out_size)
{
    const float*  t     = (const float*)d_in[0];
    const float4* ctrl4 = (const float4*)d_in[1];   // 2 ctrl pts/segment = 16B
    const F2*     joint = (const F2*)d_in[2];
    float*        out   = (float*)d_out;

    int n = in_sizes[0];
    int S = in_sizes[2] / 2 - 1;       // joint_points has (S+1)*2 floats
    float Sf = (float)S;

    int ngroups = (n + 3) / 4;
    int threads = 256;
    int blocks  = (ngroups + threads - 1) / threads;
    spline_kernel<<<blocks, threads>>>(t, ctrl4, joint, out, n, S, Sf);
}

// round 12
// speedup vs baseline: 1.5832x; 1.0122x over previous
#include <cuda_runtime.h>

// Cubic Bezier spline evaluation — 8 samples/thread, warp-uniform segment
// broadcast, packed f32x2 Horner, SMEM-staged output drained by one
// cp.async.bulk (TMA) per block.
//   d_in[0]: t              float32 [N]      (sorted, in [0,1))
//   d_in[1]: control_points float32 [S*2, 2]
//   d_in[2]: joint_points   float32 [S+1, 2]
// Output: float32 [N, 2]

struct __align__(8) F2 { float x, y; };
typedef unsigned long long u64;

__device__ __forceinline__ u64 pack2(float lo, float hi) {
    u64 r; asm("mov.b64 %0, {%1, %2};" : "=l"(r) : "f"(lo), "f"(hi)); return r;
}
__device__ __forceinline__ u64 fma2(u64 a, u64 b, u64 c) {
    u64 d; asm("fma.rn.f32x2 %0, %1, %2, %3;" : "=l"(d) : "l"(a), "l"(b), "l"(c));
    return d;
}

// Packed power-basis coefficients: each u64 is an (x, y) fp32 pair.
struct CoeffsP { u64 c0, c1, c2, c3; };

__device__ __forceinline__ CoeffsP make_coeffs(int seg,
                                               const float4* __restrict__ ctrl4,
                                               const F2* __restrict__ joint) {
    F2 P0 = joint[seg];
    F2 P3 = joint[seg + 1];
    float4 cc = ctrl4[seg];          // (P1.x, P1.y, P2.x, P2.y), 16B aligned

    CoeffsP c;
    c.c0 = pack2(P0.x, P0.y);
    c.c1 = pack2(3.0f * (cc.x - P0.x),
                 3.0f * (cc.y - P0.y));
    c.c2 = pack2(3.0f * (P0.x - 2.0f * cc.x + cc.z),
                 3.0f * (P0.y - 2.0f * cc.y + cc.w));
    c.c3 = pack2(fmaf(3.0f, cc.x - cc.z, P3.x - P0.x),
                 fmaf(3.0f, cc.y - cc.w, P3.y - P0.y));
    return c;
}

__device__ __forceinline__ u64 eval_packed(const CoeffsP& c, float lt) {
    u64 ltp = pack2(lt, lt);
    u64 acc = fma2(c.c3, ltp, c.c2);
    acc     = fma2(acc,  ltp, c.c1);
    acc     = fma2(acc,  ltp, c.c0);
    return acc;                       // (x, y) output pair
}

__device__ __forceinline__ void seg_lt(float tval, float Sf, int S,
                                       int& seg, float& lt) {
    float u = tval * Sf;               // Sf = 4096 -> exact scaling
    int   s = (int)u;                  // u >= 0 -> trunc == floor
    float l = u - (float)s;
    if (s >= S) { s = S - 1; l = 1.0f; }   // parity with reference edge case
    seg = s; lt = l;
}

// 256 threads * 8 samples * 2 floats = 4096 floats = 16 KB per block tile.
#define TILE_FLOATS 4096
#define SAMPLES_PER_THREAD 8

__global__ void __launch_bounds__(256)
spline_kernel(const float* __restrict__ t,
              const float4* __restrict__ ctrl4,
              const F2* __restrict__ joint,
              float* __restrict__ out,
              int n, int S, float Sf)
{
    __shared__ __align__(16) float tile[TILE_FLOATS];

    int tid  = threadIdx.x;
    int gid  = blockIdx.x * blockDim.x + tid;
    long long base = (long long)gid * SAMPLES_PER_THREAD;
    long long blockBase = (long long)blockIdx.x * blockDim.x * SAMPLES_PER_THREAD;
    bool fullBlock = (blockBase + TILE_FLOATS / 2) <= n;

    if (base + SAMPLES_PER_THREAD - 1 < n) {
        float4 va = *reinterpret_cast<const float4*>(t + base);
        float4 vb = *reinterpret_cast<const float4*>(t + base + 4);

        float tv[8] = {va.x, va.y, va.z, va.w, vb.x, vb.y, vb.z, vb.w};
        int   sg[8];
        float lt[8];
        #pragma unroll
        for (int k = 0; k < 8; ++k) seg_lt(tv[k], Sf, S, sg[k], lt[k]);

        // Warp spans 256 sorted samples: uniform iff first and last agree.
        unsigned mask = 0xFFFFFFFFu;
        int sFirst = __shfl_sync(mask, sg[0], 0);
        int sLast  = __shfl_sync(mask, sg[7], 31);

        ulonglong2* tp = fullBlock
            ? reinterpret_cast<ulonglong2*>(tile) + tid * 4
            : reinterpret_cast<ulonglong2*>(out + 2 * base);

        if (sFirst == sLast) {
            // Uniform path (~87% of warps): broadcast gather, one assembly.
            CoeffsP c = make_coeffs(sFirst, ctrl4, joint);
            #pragma unroll
            for (int k = 0; k < 8; k += 2) {
                u64 ra = eval_packed(c, lt[k]);
                u64 rb = eval_packed(c, lt[k + 1]);
                tp[k >> 1] = make_ulonglong2(ra, rb);
            }
        } else {
            #pragma unroll
            for (int k = 0; k < 8; k += 2) {
                CoeffsP ca = make_coeffs(sg[k], ctrl4, joint);
                u64 ra = eval_packed(ca, lt[k]);
                CoeffsP cb = make_coeffs(sg[k + 1], ctrl4, joint);
                u64 rb = eval_packed(cb, lt[k + 1]);
                tp[k >> 1] = make_ulonglong2(ra, rb);
            }
        }
    } else {
        for (long long k = base; k < n; ++k) {
            int s; float l;
            seg_lt(t[k], Sf, S, s, l);
            CoeffsP c = make_coeffs(s, ctrl4, joint);
            reinterpret_cast<u64*>(out)[k] = eval_packed(c, l);
        }
    }

    if (fullBlock) {
        __syncthreads();
        if (tid == 0) {
            // Order generic smem stores before the async-proxy bulk copy.
            asm volatile("fence.proxy.async.shared::cta;" ::: "memory");
            unsigned saddr;
            asm("{ .reg .u64 tmp; cvta.to.shared.u64 tmp, %1; cvt.u32.u64 %0, tmp; }"
                : "=r"(saddr) : "l"(tile));
            float* gdst = out + 2 * blockBase;
            asm volatile("cp.async.bulk.global.shared::cta.bulk_group [%0], [%1], %2;"
                         :: "l"(gdst), "r"(saddr), "n"(TILE_FLOATS * 4) : "memory");
            asm volatile("cp.async.bulk.commit_group;" ::: "memory");
            asm volatile("cp.async.bulk.wait_group 0;" ::: "memory");
        }
    }
}

extern "C" void kernel_launch(void* const* d_in, const int* in_sizes, int n_in,
                              void* d_out, int out_size)
{
    const float*  t     = (const float*)d_in[0];
    const float4* ctrl4 = (const float4*)d_in[1];   // 2 ctrl pts/segment = 16B
    const F2*     joint = (const F2*)d_in[2];
    float*        out   = (float*)d_out;

    int n = in_sizes[0];
    int S = in_sizes[2] / 2 - 1;       // joint_points has (S+1)*2 floats
    float Sf = (float)S;

    int ngroups = (n + SAMPLES_PER_THREAD - 1) / SAMPLES_PER_THREAD;
    int threads = 256;
    int blocks  = (ngroups + threads - 1) / threads;
    spline_kernel<<<blocks, threads>>>(t, ctrl4, joint, out, n, S, Sf);
}

// round 16
// speedup vs baseline: 1.7547x; 1.1083x over previous
#include <cuda_runtime.h>

// Cubic Bezier spline evaluation — R11 structure (4 samples/thread, 256 thr,
// 8 KB smem tile + one cp.async.bulk drain per block, warp-uniform segment
// broadcast) + packed f32x2 Horner math.  (Resubmission of R13 — prior round
// was an infra failure, kernel never executed.)
//   d_in[0]: t              float32 [N]      (sorted, in [0,1))
//   d_in[1]: control_points float32 [S*2, 2]
//   d_in[2]: joint_points   float32 [S+1, 2]
// Output: float32 [N, 2]

struct __align__(8) F2 { float x, y; };
typedef unsigned long long u64;

__device__ __forceinline__ u64 pack2(float lo, float hi) {
    u64 r; asm("mov.b64 %0, {%1, %2};" : "=l"(r) : "f"(lo), "f"(hi)); return r;
}
__device__ __forceinline__ u64 fma2(u64 a, u64 b, u64 c) {
    u64 d; asm("fma.rn.f32x2 %0, %1, %2, %3;" : "=l"(d) : "l"(a), "l"(b), "l"(c));
    return d;
}

// Packed power-basis coefficients: each u64 is an (x, y) fp32 pair.
struct CoeffsP { u64 c0, c1, c2, c3; };

__device__ __forceinline__ CoeffsP make_coeffs(int seg,
                                               const float4* __restrict__ ctrl4,
                                               const F2* __restrict__ joint) {
    F2 P0 = joint[seg];
    F2 P3 = joint[seg + 1];
    float4 cc = ctrl4[seg];          // (P1.x, P1.y, P2.x, P2.y), 16B aligned

    CoeffsP c;
    c.c0 = pack2(P0.x, P0.y);
    c.c1 = pack2(3.0f * (cc.x - P0.x),
                 3.0f * (cc.y - P0.y));
    c.c2 = pack2(3.0f * (P0.x - 2.0f * cc.x + cc.z),
                 3.0f * (P0.y - 2.0f * cc.y + cc.w));
    c.c3 = pack2(fmaf(3.0f, cc.x - cc.z, P3.x - P0.x),
                 fmaf(3.0f, cc.y - cc.w, P3.y - P0.y));
    return c;
}

__device__ __forceinline__ u64 eval_packed(const CoeffsP& c, float lt) {
    u64 ltp = pack2(lt, lt);
    u64 acc = fma2(c.c3, ltp, c.c2);
    acc     = fma2(acc,  ltp, c.c1);
    acc     = fma2(acc,  ltp, c.c0);
    return acc;                       // (x, y) output pair
}

__device__ __forceinline__ void seg_lt(float tval, float Sf, int S,
                                       int& seg, float& lt) {
    float u = tval * Sf;               // Sf = 4096 -> exact scaling
    int   s = (int)u;                  // u >= 0 -> trunc == floor
    float l = u - (float)s;
    if (s >= S) { s = S - 1; l = 1.0f; }   // parity with reference edge case
    seg = s; lt = l;
}

// 256 threads * 4 samples * 2 floats = 2048 floats = 8 KB per block tile.
#define TILE_FLOATS 2048

__global__ void __launch_bounds__(256)
spline_kernel(const float* __restrict__ t,
              const float4* __restrict__ ctrl4,
              const F2* __restrict__ joint,
              float* __restrict__ out,
              int n, int S, float Sf)
{
    __shared__ __align__(16) float tile[TILE_FLOATS];

    int tid  = threadIdx.x;
    int gid  = blockIdx.x * blockDim.x + tid;   // group of 4 samples
    int base = gid * 4;
    int blockBase = blockIdx.x * (int)blockDim.x * 4;       // first sample of block
    bool fullBlock = (blockBase + TILE_FLOATS / 2) <= n;    // all 1024 samples valid

    if (base + 3 < n) {
        float4 tv = *reinterpret_cast<const float4*>(t + base);

        int   sg[4];
        float lt[4];
        seg_lt(tv.x, Sf, S, sg[0], lt[0]);
        seg_lt(tv.y, Sf, S, sg[1], lt[1]);
        seg_lt(tv.z, Sf, S, sg[2], lt[2]);
        seg_lt(tv.w, Sf, S, sg[3], lt[3]);

        // Warp spans 128 sorted samples: uniform iff first and last agree.
        unsigned mask = 0xFFFFFFFFu;
        int sFirst = __shfl_sync(mask, sg[0], 0);
        int sLast  = __shfl_sync(mask, sg[3], 31);

        ulonglong2* tp = fullBlock
            ? reinterpret_cast<ulonglong2*>(tile) + tid * 2
            : reinterpret_cast<ulonglong2*>(out + 2 * base);

        if (sFirst == sLast) {
            // Uniform path (~94% of warps): broadcast gather, one assembly.
            CoeffsP c = make_coeffs(sFirst, ctrl4, joint);
            u64 r0 = eval_packed(c, lt[0]);
            u64 r1 = eval_packed(c, lt[1]);
            tp[0] = make_ulonglong2(r0, r1);
            u64 r2 = eval_packed(c, lt[2]);
            u64 r3 = eval_packed(c, lt[3]);
            tp[1] = make_ulonglong2(r2, r3);
        } else {
            CoeffsP ca = make_coeffs(sg[0], ctrl4, joint);
            u64 r0 = eval_packed(ca, lt[0]);
            CoeffsP cb = make_coeffs(sg[1], ctrl4, joint);
            u64 r1 = eval_packed(cb, lt[1]);
            tp[0] = make_ulonglong2(r0, r1);
            CoeffsP cc = make_coeffs(sg[2], ctrl4, joint);
            u64 r2 = eval_packed(cc, lt[2]);
            CoeffsP cd = make_coeffs(sg[3], ctrl4, joint);
            u64 r3 = eval_packed(cd, lt[3]);
            tp[1] = make_ulonglong2(r2, r3);
        }
    } else {
        for (int k = base; k < n; ++k) {
            int s; float l;
            seg_lt(t[k], Sf, S, s, l);
            CoeffsP c = make_coeffs(s, ctrl4, joint);
            reinterpret_cast<u64*>(out)[k] = eval_packed(c, l);
        }
    }

    if (fullBlock) {
        __syncthreads();
        if (tid == 0) {
            // Order generic smem stores before the async-proxy bulk copy.
            asm volatile("fence.proxy.async.shared::cta;" ::: "memory");
            unsigned saddr;
            asm("{ .reg .u64 tmp; cvta.to.shared.u64 tmp, %1; cvt.u32.u64 %0, tmp; }"
                : "=r"(saddr) : "l"(tile));
            float* gdst = out + 2 * blockBase;
            asm volatile("cp.async.bulk.global.shared::cta.bulk_group [%0], [%1], %2;"
                         :: "l"(gdst), "r"(saddr), "n"(TILE_FLOATS * 4) : "memory");
            asm volatile("cp.async.bulk.commit_group;" ::: "memory");
            asm volatile("cp.async.bulk.wait_group 0;" ::: "memory");
        }
    }
}

extern "C" void kernel_launch(void* const* d_in, const int* in_sizes, int n_in,
                              void* d_out, int out_size)
{
    const float*  t     = (const float*)d_in[0];
    const float4* ctrl4 = (const float4*)d_in[1];   // 2 ctrl pts/segment = 16B
    const F2*     joint = (const F2*)d_in[2];
    float*        out   = (float*)d_out;

    int n = in_sizes[0];
    int S = in_sizes[2] / 2 - 1;       // joint_points has (S+1)*2 floats
    float Sf = (float)S;

    int ngroups = (n + 3) / 4;
    int threads = 256;
    int blocks  = (ngroups + threads - 1) / threads;
    spline_kernel<<<blocks, threads>>>(t, ctrl4, joint, out, n, S, Sf);
}